// round 4
// baseline (speedup 1.0000x reference)
#include <cuda_runtime.h>
#include <math.h>
#include <stdint.h>

#define Bc 4
#define Sc 1024
#define Dc 512
#define Hc 8
#define DHc 64
#define DIc 2048
#define Lc 12
#define Vc 10000
#define M_ROWS (Bc*Sc)   /* 4096 */

// ---------------- scratch (no allocations allowed) ----------------
__device__ float g_h  [M_ROWS*Dc];
__device__ float g_q  [M_ROWS*Dc];
__device__ float g_kv [M_ROWS*2*Dc];
__device__ float g_ao [M_ROWS*Dc];
__device__ float g_tmp[M_ROWS*Dc];
__device__ float g_ff [M_ROWS*DIc];

// ---------------- embedding ----------------
__global__ void embed_kernel(const int* __restrict__ data,
                             const float* __restrict__ we,
                             const float* __restrict__ pe,
                             float* __restrict__ h) {
    int i = blockIdx.x * blockDim.x + threadIdx.x;
    if (i >= M_ROWS * Dc) return;
    int d   = i % Dc;
    int row = i / Dc;
    int s   = row % Sc;
    int tok = data[row];
    h[i] = we[(size_t)tok * Dc + d] + pe[(size_t)s * Dc + d];
}

// ---------------- tf32 helpers ----------------------------------------------
__device__ __forceinline__ uint32_t f2tf32(float f) {
    uint32_t r;
    asm("cvt.rna.tf32.f32 %0, %1;" : "=r"(r) : "f"(f));
    return r;
}

__device__ __forceinline__ void cp16(void* smem, const void* g, int srcBytes) {
    uint32_t s = (uint32_t)__cvta_generic_to_shared(smem);
    asm volatile("cp.async.cg.shared.global [%0], [%1], 16, %2;\n"
                 :: "r"(s), "l"(g), "r"(srcBytes));
}

__device__ __forceinline__ void mma_tf32(float c[4],
    uint32_t a0, uint32_t a1, uint32_t a2, uint32_t a3,
    uint32_t b0, uint32_t b1)
{
    asm volatile(
        "mma.sync.aligned.m16n8k8.row.col.f32.tf32.tf32.f32 "
        "{%0,%1,%2,%3}, {%4,%5,%6,%7}, {%8,%9}, {%0,%1,%2,%3};"
        : "+f"(c[0]), "+f"(c[1]), "+f"(c[2]), "+f"(c[3])
        : "r"(a0), "r"(a1), "r"(a2), "r"(a3), "r"(b0), "r"(b1));
}

// ---------------- tf32 tensor-core GEMM --------------------------------------
// C[M,N] = A[M,K] @ W[N,K]^T (+bias)(+res)(relu?)   M % 128 == 0, K % 16 == 0
// outMode: 0 = float out, 1 = tf32-bit out, 2 = tf32-bit out with 0.125 scale
#define TBM 128
#define TBN 128
#define TBK 16
#define TPITCH 20
#define STAGES 4
#define TGEMM_SMEM (STAGES * (TBM + TBN) * TPITCH * 4)

extern __shared__ float dyn_smem[];

__global__ __launch_bounds__(256) void tgemm_kernel(
    const float* __restrict__ A, const float* __restrict__ W,
    const float* __restrict__ bias, const float* __restrict__ res,
    float* __restrict__ C, int M, int N, int K, int doRelu, int outMode)
{
    float* As = dyn_smem;                                // [STAGES][TBM][TPITCH]
    float* Bs = dyn_smem + STAGES * TBM * TPITCH;        // [STAGES][TBN][TPITCH]

    const int tid  = threadIdx.x;
    const int lane = tid & 31;
    const int warp = tid >> 5;
    const int wm   = warp >> 2;
    const int wn   = warp & 3;
    const int bm   = blockIdx.y * TBM;
    const int bn   = blockIdx.x * TBN;

    const int ldr = tid >> 2;          // 0..63
    const int kc  = (tid & 3) * 4;     // 0,4,8,12

    float acc[4][4][4];
    #pragma unroll
    for (int i = 0; i < 4; i++)
        #pragma unroll
        for (int j = 0; j < 4; j++)
            #pragma unroll
            for (int t = 0; t < 4; t++) acc[i][j][t] = 0.f;

    const int KT = K / TBK;

    // prologue: tiles 0..STAGES-2
    #pragma unroll
    for (int s = 0; s < STAGES - 1; s++) {
        if (s < KT) {
            int k0 = s * TBK;
            float* Asb = As + s * TBM * TPITCH;
            float* Bsb = Bs + s * TBN * TPITCH;
            #pragma unroll
            for (int p = 0; p < 2; p++) {
                int r = ldr + p * 64;
                cp16(Asb + r * TPITCH + kc, A + (size_t)(bm + r) * K + k0 + kc, 16);
            }
            #pragma unroll
            for (int p = 0; p < 2; p++) {
                int r  = ldr + p * 64;
                int gn = bn + r;
                int ok = (gn < N) ? 16 : 0;
                int gc = (gn < N) ? gn : (N - 1);
                cp16(Bsb + r * TPITCH + kc, W + (size_t)gc * K + k0 + kc, ok);
            }
        }
        asm volatile("cp.async.commit_group;\n");
    }

    for (int t = 0; t < KT; t++) {
        asm volatile("cp.async.wait_group 2;\n");
        __syncthreads();

        // prefetch tile t+STAGES-1
        {
            int tp = t + STAGES - 1;
            if (tp < KT) {
                int sb = tp % STAGES;
                int k0 = tp * TBK;
                float* Asb = As + sb * TBM * TPITCH;
                float* Bsb = Bs + sb * TBN * TPITCH;
                #pragma unroll
                for (int p = 0; p < 2; p++) {
                    int r = ldr + p * 64;
                    cp16(Asb + r * TPITCH + kc, A + (size_t)(bm + r) * K + k0 + kc, 16);
                }
                #pragma unroll
                for (int p = 0; p < 2; p++) {
                    int r  = ldr + p * 64;
                    int gn = bn + r;
                    int ok = (gn < N) ? 16 : 0;
                    int gc = (gn < N) ? gn : (N - 1);
                    cp16(Bsb + r * TPITCH + kc, W + (size_t)gc * K + k0 + kc, ok);
                }
            }
            asm volatile("cp.async.commit_group;\n");
        }

        const int buf = t % STAGES;
        float* Asb = As + buf * TBM * TPITCH;
        float* Bsb = Bs + buf * TBN * TPITCH;

        // in-place tf32 conversion of this stage (each thread converts what it loaded)
        {
            uint32_t* Au = (uint32_t*)Asb;
            uint32_t* Bu = (uint32_t*)Bsb;
            #pragma unroll
            for (int p = 0; p < 2; p++) {
                int base = (ldr + p * 64) * TPITCH + kc;
                #pragma unroll
                for (int j = 0; j < 4; j++) {
                    Au[base + j] = f2tf32(Asb[base + j]);
                    Bu[base + j] = f2tf32(Bsb[base + j]);
                }
            }
        }
        __syncthreads();

        const uint32_t* Au = (const uint32_t*)Asb;
        const uint32_t* Bu = (const uint32_t*)Bsb;
        #pragma unroll
        for (int ks = 0; ks < 2; ks++) {
            const int col = ks * 8 + (lane & 3);
            const int ra  = wm * 64 + (lane >> 2);
            const int rb  = wn * 32 + (lane >> 2);

            uint32_t af[4][4], bf[4][2];
            #pragma unroll
            for (int mi = 0; mi < 4; mi++) {
                af[mi][0] = Au[(ra + mi * 16    ) * TPITCH + col];
                af[mi][1] = Au[(ra + mi * 16 + 8) * TPITCH + col];
                af[mi][2] = Au[(ra + mi * 16    ) * TPITCH + col + 4];
                af[mi][3] = Au[(ra + mi * 16 + 8) * TPITCH + col + 4];
            }
            #pragma unroll
            for (int ni = 0; ni < 4; ni++) {
                bf[ni][0] = Bu[(rb + ni * 8) * TPITCH + col];
                bf[ni][1] = Bu[(rb + ni * 8) * TPITCH + col + 4];
            }
            #pragma unroll
            for (int mi = 0; mi < 4; mi++)
                #pragma unroll
                for (int ni = 0; ni < 4; ni++)
                    mma_tf32(acc[mi][ni], af[mi][0], af[mi][1], af[mi][2], af[mi][3],
                             bf[ni][0], bf[ni][1]);
        }
        __syncthreads();
    }

    const int lr = lane >> 2;
    const int lc = (lane & 3) * 2;
    #pragma unroll
    for (int mi = 0; mi < 4; mi++) {
        int r0 = bm + wm * 64 + mi * 16 + lr;
        #pragma unroll
        for (int ni = 0; ni < 4; ni++) {
            int c0 = bn + wn * 32 + ni * 8 + lc;
            if (c0 >= N) continue;
            float v0 = acc[mi][ni][0], v1 = acc[mi][ni][1];
            float v2 = acc[mi][ni][2], v3 = acc[mi][ni][3];
            if (bias) {
                float b0 = bias[c0], b1 = bias[c0 + 1];
                v0 += b0; v1 += b1; v2 += b0; v3 += b1;
            }
            if (res) {
                v0 += res[(size_t)r0 * N + c0];
                v1 += res[(size_t)r0 * N + c0 + 1];
                v2 += res[(size_t)(r0 + 8) * N + c0];
                v3 += res[(size_t)(r0 + 8) * N + c0 + 1];
            }
            if (doRelu) {
                v0 = fmaxf(v0, 0.f); v1 = fmaxf(v1, 0.f);
                v2 = fmaxf(v2, 0.f); v3 = fmaxf(v3, 0.f);
            }
            if (outMode) {
                float s = (outMode == 2) ? 0.125f : 1.f;
                v0 = __uint_as_float(f2tf32(v0 * s));
                v1 = __uint_as_float(f2tf32(v1 * s));
                v2 = __uint_as_float(f2tf32(v2 * s));
                v3 = __uint_as_float(f2tf32(v3 * s));
            }
            *(float2*)&C[(size_t)r0 * N + c0]       = make_float2(v0, v1);
            *(float2*)&C[(size_t)(r0 + 8) * N + c0] = make_float2(v2, v3);
        }
    }
}

// ---------------- tensor-core flash attention v2 ------------------------------
// 64q x 64k tiles, 4 warps. Q/K/V arrive as tf32 bits (pre-converted by tgemm).
// In-register online softmax (quad shuffles), cp.async double-buffered K/V.
#define AP 68
#define FATTN_SMEM ((6 * 64 * AP) * 4)

__global__ __launch_bounds__(128) void fattn_tc(
    const float* __restrict__ Q, const float* __restrict__ Kb,
    const float* __restrict__ Vb, float* __restrict__ O)
{
    float* Qs  = dyn_smem;              // [64][AP] tf32 bits
    float* Ks  = Qs + 64 * AP;          // 2 x [64][AP]
    float* Vk  = Ks + 2 * 64 * AP;      // 2 x [64][AP] (row k, col d — untransposed)
    float* Ss  = Vk + 2 * 64 * AP;      // [64][AP] P bits

    const int qt = (gridDim.x - 1) - blockIdx.x;   // big tiles first
    const int h  = blockIdx.y, b = blockIdx.z;
    const int q0 = qt * 64;
    const int tid  = threadIdx.x;
    const int lane = tid & 31;
    const int warp = tid >> 5;

    const int QSTR  = Hc * DHc;         // 512
    const int KVSTR = 2 * Hc * DHc;     // 1024

    const int r0  = warp * 16 + (lane >> 2);
    const int cq  = lane & 3;
    const int ls4 = lane >> 2;

    // load Q tile (already tf32 bits, pre-scaled)
    #pragma unroll
    for (int p = 0; p < 8; p++) {
        int c = tid + p * 128;
        int r = c >> 4, d4 = (c & 15) * 4;
        float4 v = *(const float4*)(Q + (size_t)(b * Sc + q0 + r) * QSTR + h * DHc + d4);
        *(float4*)&Qs[r * AP + d4] = v;
    }

    float o_acc[8][4];
    #pragma unroll
    for (int n = 0; n < 8; n++)
        #pragma unroll
        for (int t = 0; t < 4; t++) o_acc[n][t] = 0.f;
    float m0 = -1e30f, m1 = -1e30f, l0 = 0.f, l1 = 0.f;

    const int nt = qt + 1;
    const size_t kvrow0 = (size_t)(b * Sc) * KVSTR + h * DHc;

    // prologue: tile 0 into buf 0
    #pragma unroll
    for (int p = 0; p < 8; p++) {
        int c = tid + p * 128;
        int r = c >> 4, d4 = (c & 15) * 4;
        cp16(&Ks[r * AP + d4], Kb + kvrow0 + (size_t)r * KVSTR + d4, 16);
        cp16(&Vk[r * AP + d4], Vb + kvrow0 + (size_t)r * KVSTR + d4, 16);
    }
    asm volatile("cp.async.commit_group;\n");

    for (int kt = 0; kt < nt; kt++) {
        asm volatile("cp.async.wait_group 0;\n");
        __syncthreads();

        const int buf = kt & 1;
        // prefetch next tile into other buffer
        if (kt + 1 < nt) {
            const int nb = buf ^ 1;
            const size_t base = kvrow0 + (size_t)(kt + 1) * 64 * KVSTR;
            #pragma unroll
            for (int p = 0; p < 8; p++) {
                int c = tid + p * 128;
                int r = c >> 4, d4 = (c & 15) * 4;
                cp16(&Ks[nb * 64 * AP + r * AP + d4], Kb + base + (size_t)r * KVSTR + d4, 16);
                cp16(&Vk[nb * 64 * AP + r * AP + d4], Vb + base + (size_t)r * KVSTR + d4, 16);
            }
        }
        asm volatile("cp.async.commit_group;\n");

        const uint32_t* Qu = (const uint32_t*)Qs;
        const uint32_t* Ku = (const uint32_t*)(Ks + buf * 64 * AP);
        const uint32_t* Vu = (const uint32_t*)(Vk + buf * 64 * AP);
        uint32_t*       Pu = (uint32_t*)Ss;

        // S = Q @ K^T
        float sacc[8][4];
        #pragma unroll
        for (int n = 0; n < 8; n++)
            #pragma unroll
            for (int t = 0; t < 4; t++) sacc[n][t] = 0.f;

        #pragma unroll
        for (int k8 = 0; k8 < 8; k8++) {
            const int kcol = k8 * 8 + cq;
            uint32_t a0 = Qu[ r0      * AP + kcol];
            uint32_t a1 = Qu[(r0 + 8) * AP + kcol];
            uint32_t a2 = Qu[ r0      * AP + kcol + 4];
            uint32_t a3 = Qu[(r0 + 8) * AP + kcol + 4];
            #pragma unroll
            for (int n = 0; n < 8; n++) {
                const int nr = n * 8 + ls4;
                mma_tf32(sacc[n], a0, a1, a2, a3,
                         Ku[nr * AP + kcol], Ku[nr * AP + kcol + 4]);
            }
        }

        // causal mask on diagonal tile (k0 == q0)
        if (kt == qt) {
            #pragma unroll
            for (int n = 0; n < 8; n++) {
                const int c0 = n * 8 + cq * 2;
                if (c0     > r0)     sacc[n][0] = -1e30f;
                if (c0 + 1 > r0)     sacc[n][1] = -1e30f;
                if (c0     > r0 + 8) sacc[n][2] = -1e30f;
                if (c0 + 1 > r0 + 8) sacc[n][3] = -1e30f;
            }
        }

        // in-register online softmax (rows owned warp-locally; quad reduce)
        float mx0 = -1e30f, mx1 = -1e30f;
        #pragma unroll
        for (int n = 0; n < 8; n++) {
            mx0 = fmaxf(mx0, fmaxf(sacc[n][0], sacc[n][1]));
            mx1 = fmaxf(mx1, fmaxf(sacc[n][2], sacc[n][3]));
        }
        mx0 = fmaxf(mx0, __shfl_xor_sync(0xffffffffu, mx0, 1));
        mx0 = fmaxf(mx0, __shfl_xor_sync(0xffffffffu, mx0, 2));
        mx1 = fmaxf(mx1, __shfl_xor_sync(0xffffffffu, mx1, 1));
        mx1 = fmaxf(mx1, __shfl_xor_sync(0xffffffffu, mx1, 2));

        const float mn0 = fmaxf(m0, mx0);
        const float mn1 = fmaxf(m1, mx1);
        const float cr0 = __expf(m0 - mn0);
        const float cr1 = __expf(m1 - mn1);
        float s0 = 0.f, s1 = 0.f;
        #pragma unroll
        for (int n = 0; n < 8; n++) {
            float p00 = __expf(sacc[n][0] - mn0);
            float p01 = __expf(sacc[n][1] - mn0);
            float p10 = __expf(sacc[n][2] - mn1);
            float p11 = __expf(sacc[n][3] - mn1);
            s0 += p00 + p01;
            s1 += p10 + p11;
            const int c0 = n * 8 + cq * 2;
            uint2 w0 = make_uint2(f2tf32(p00), f2tf32(p01));
            uint2 w1 = make_uint2(f2tf32(p10), f2tf32(p11));
            *(uint2*)&Pu[ r0      * AP + c0] = w0;
            *(uint2*)&Pu[(r0 + 8) * AP + c0] = w1;
        }
        s0 += __shfl_xor_sync(0xffffffffu, s0, 1);
        s0 += __shfl_xor_sync(0xffffffffu, s0, 2);
        s1 += __shfl_xor_sync(0xffffffffu, s1, 1);
        s1 += __shfl_xor_sync(0xffffffffu, s1, 2);

        l0 = l0 * cr0 + s0;  m0 = mn0;
        l1 = l1 * cr1 + s1;  m1 = mn1;
        #pragma unroll
        for (int n = 0; n < 8; n++) {
            o_acc[n][0] *= cr0; o_acc[n][1] *= cr0;
            o_acc[n][2] *= cr1; o_acc[n][3] *= cr1;
        }
        __syncwarp();

        // O += P @ V   (B read from untransposed Vk: element V[k][d] at Vu[k*AP + d])
        #pragma unroll
        for (int k8 = 0; k8 < 8; k8++) {
            const int kcol = k8 * 8 + cq;
            uint32_t a0 = Pu[ r0      * AP + kcol];
            uint32_t a1 = Pu[(r0 + 8) * AP + kcol];
            uint32_t a2 = Pu[ r0      * AP + kcol + 4];
            uint32_t a3 = Pu[(r0 + 8) * AP + kcol + 4];
            #pragma unroll
            for (int n = 0; n < 8; n++) {
                const int nr = n * 8 + ls4;
                mma_tf32(o_acc[n], a0, a1, a2, a3,
                         Vu[kcol * AP + nr], Vu[(kcol + 4) * AP + nr]);
            }
        }
    }

    const float inv0 = 1.f / l0;
    const float inv1 = 1.f / l1;
    #pragma unroll
    for (int n = 0; n < 8; n++) {
        const int c0 = n * 8 + cq * 2;
        size_t o0 = (size_t)(b * Sc + q0 + r0)     * QSTR + h * DHc + c0;
        size_t o1 = (size_t)(b * Sc + q0 + r0 + 8) * QSTR + h * DHc + c0;
        *(float2*)&O[o0] = make_float2(o_acc[n][0] * inv0, o_acc[n][1] * inv0);
        *(float2*)&O[o1] = make_float2(o_acc[n][2] * inv1, o_acc[n][3] * inv1);
    }
}

// ---------------- LayerNorm over D=512 --------------------------------------
__global__ void ln_kernel(const float* __restrict__ X, const float* __restrict__ g,
                          const float* __restrict__ bta, float* __restrict__ Y) {
    int row = blockIdx.x;
    const float* x = X + (size_t)row * Dc;
    float* y = Y + (size_t)row * Dc;
    int tid = threadIdx.x;

    float v[4];
    float sum = 0.f;
    #pragma unroll
    for (int i = 0; i < 4; i++) { v[i] = x[tid + i*128]; sum += v[i]; }

    __shared__ float red[4];
    #pragma unroll
    for (int off = 16; off; off >>= 1) sum += __shfl_xor_sync(0xffffffffu, sum, off);
    if ((tid & 31) == 0) red[tid >> 5] = sum;
    __syncthreads();
    sum = red[0] + red[1] + red[2] + red[3];
    float mean = sum * (1.f / Dc);

    float sq = 0.f;
    #pragma unroll
    for (int i = 0; i < 4; i++) { float d = v[i] - mean; sq += d * d; }
    __shared__ float red2[4];
    #pragma unroll
    for (int off = 16; off; off >>= 1) sq += __shfl_xor_sync(0xffffffffu, sq, off);
    if ((tid & 31) == 0) red2[tid >> 5] = sq;
    __syncthreads();
    sq = red2[0] + red2[1] + red2[2] + red2[3];
    float rstd = rsqrtf(sq * (1.f / Dc) + 1e-5f);

    #pragma unroll
    for (int i = 0; i < 4; i++) {
        int d = tid + i*128;
        y[d] = (v[i] - mean) * rstd * g[d] + bta[d];
    }
}

// ---------------- launch ----------------------------------------------------
extern "C" void kernel_launch(void* const* d_in, const int* in_sizes, int n_in,
                              void* d_out, int out_size) {
    const int*   data = (const int*)  d_in[0];
    const float* we   = (const float*)d_in[1];
    const float* pe   = (const float*)d_in[2];
    const float* Wq   = (const float*)d_in[3];
    const float* Wkv  = (const float*)d_in[4];
    const float* Wo   = (const float*)d_in[5];
    const float* g1   = (const float*)d_in[6];
    const float* bl1  = (const float*)d_in[7];
    const float* W1   = (const float*)d_in[8];
    const float* bf1  = (const float*)d_in[9];
    const float* W2   = (const float*)d_in[10];
    const float* bf2  = (const float*)d_in[11];
    const float* g2   = (const float*)d_in[12];
    const float* bl2  = (const float*)d_in[13];
    const float* outb = (const float*)d_in[14];
    float* out = (float*)d_out;

    float *h, *q, *kv, *ao, *tmp, *ff;
    cudaGetSymbolAddress((void**)&h,   g_h);
    cudaGetSymbolAddress((void**)&q,   g_q);
    cudaGetSymbolAddress((void**)&kv,  g_kv);
    cudaGetSymbolAddress((void**)&ao,  g_ao);
    cudaGetSymbolAddress((void**)&tmp, g_tmp);
    cudaGetSymbolAddress((void**)&ff,  g_ff);

    cudaFuncSetAttribute(tgemm_kernel, cudaFuncAttributeMaxDynamicSharedMemorySize, TGEMM_SMEM);
    cudaFuncSetAttribute(fattn_tc,     cudaFuncAttributeMaxDynamicSharedMemorySize, FATTN_SMEM);

    embed_kernel<<<(M_ROWS*Dc + 255)/256, 256>>>(data, we, pe, h);

    dim3 gsD (( Dc   + 127)/128, M_ROWS/128);
    dim3 gsKV((2*Dc  + 127)/128, M_ROWS/128);
    dim3 gsDI(( DIc  + 127)/128, M_ROWS/128);
    dim3 gsV (( Vc   + 127)/128, M_ROWS/128);
    dim3 gsA (Sc/64, Hc, Bc);

    for (int l = 0; l < Lc; l++) {
        const float* wq  = Wq  + (size_t)l * Dc * Dc;
        const float* wkv = Wkv + (size_t)l * 2 * Dc * Dc;
        const float* wo  = Wo  + (size_t)l * Dc * Dc;

        tgemm_kernel<<<gsD,  256, TGEMM_SMEM>>>(h, wq,  nullptr, nullptr, q,  M_ROWS, Dc,   Dc, 0, 2);
        tgemm_kernel<<<gsKV, 256, TGEMM_SMEM>>>(h, wkv, nullptr, nullptr, kv, M_ROWS, 2*Dc, Dc, 0, 1);

        fattn_tc<<<gsA, 128, FATTN_SMEM>>>(q, kv, kv + Dc, ao);

        tgemm_kernel<<<gsD, 256, TGEMM_SMEM>>>(ao, wo, nullptr, h, tmp, M_ROWS, Dc, Dc, 0, 0);
        ln_kernel<<<M_ROWS, 128>>>(tmp, g1 + (size_t)l*Dc, bl1 + (size_t)l*Dc, h);

        tgemm_kernel<<<gsDI, 256, TGEMM_SMEM>>>(h,  W1 + (size_t)l*DIc*Dc, bf1 + (size_t)l*DIc, nullptr, ff,  M_ROWS, DIc, Dc,  1, 0);
        tgemm_kernel<<<gsD,  256, TGEMM_SMEM>>>(ff, W2 + (size_t)l*Dc*DIc, bf2 + (size_t)l*Dc,  h,       tmp, M_ROWS, Dc,  DIc, 0, 0);
        ln_kernel<<<M_ROWS, 128>>>(tmp, g2 + (size_t)l*Dc, bl2 + (size_t)l*Dc, h);
    }

    tgemm_kernel<<<gsV, 256, TGEMM_SMEM>>>(h, we, outb, nullptr, out, M_ROWS, Vc, Dc, 0, 0);
}

// round 5
// speedup vs baseline: 1.1908x; 1.1908x over previous
#include <cuda_runtime.h>
#include <math.h>
#include <stdint.h>

#define Bc 4
#define Sc 1024
#define Dc 512
#define Hc 8
#define DHc 64
#define DIc 2048
#define Lc 12
#define Vc 10000
#define M_ROWS (Bc*Sc)   /* 4096 */
#define QKVSTR (3*Dc)    /* 1536 */

// ---------------- scratch (no allocations allowed) ----------------
__device__ float g_h   [M_ROWS*Dc];
__device__ float g_qkv [M_ROWS*QKVSTR];
__device__ float g_ao  [M_ROWS*Dc];
__device__ float g_tmp [M_ROWS*Dc];
__device__ float g_ff  [M_ROWS*DIc];
// tf32-preconverted weights
__device__ float g_wqkv[Lc*QKVSTR*Dc];   // [l][1536][512]: rows 0..511 = Wq*0.125, 512..1535 = Wkv
__device__ float g_wo_t[Lc*Dc*Dc];
__device__ float g_w1_t[Lc*DIc*Dc];
__device__ float g_w2_t[Lc*Dc*DIc];
__device__ float g_we_t[Vc*Dc];

// ---------------- tf32 helpers ----------------------------------------------
__device__ __forceinline__ uint32_t f2tf32(float f) {
    uint32_t r;
    asm("cvt.rna.tf32.f32 %0, %1;" : "=r"(r) : "f"(f));
    return r;
}

__device__ __forceinline__ void cp16(void* smem, const void* g, int srcBytes) {
    uint32_t s = (uint32_t)__cvta_generic_to_shared(smem);
    asm volatile("cp.async.cg.shared.global [%0], [%1], 16, %2;\n"
                 :: "r"(s), "l"(g), "r"(srcBytes));
}

__device__ __forceinline__ void mma_tf32(float c[4],
    uint32_t a0, uint32_t a1, uint32_t a2, uint32_t a3,
    uint32_t b0, uint32_t b1)
{
    asm volatile(
        "mma.sync.aligned.m16n8k8.row.col.f32.tf32.tf32.f32 "
        "{%0,%1,%2,%3}, {%4,%5,%6,%7}, {%8,%9}, {%0,%1,%2,%3};"
        : "+f"(c[0]), "+f"(c[1]), "+f"(c[2]), "+f"(c[3])
        : "r"(a0), "r"(a1), "r"(a2), "r"(a3), "r"(b0), "r"(b1));
}

// ---------------- weight preconversion ---------------------------------------
__global__ void pack_qkv_w(const float* __restrict__ Wq, const float* __restrict__ Wkv,
                           float* __restrict__ dst) {
    int i = blockIdx.x * blockDim.x + threadIdx.x;
    if (i >= Lc * QKVSTR * Dc) return;
    int c = i % Dc;
    int r = (i / Dc) % QKVSTR;
    int l = i / (Dc * QKVSTR);
    float v;
    if (r < Dc) v = Wq[((size_t)l * Dc + r) * Dc + c] * 0.125f;
    else        v = Wkv[((size_t)l * 2 * Dc + (r - Dc)) * Dc + c];
    dst[i] = __uint_as_float(f2tf32(v));
}

__global__ void cvt_w(const float* __restrict__ src, float* __restrict__ dst, int n) {
    int i = blockIdx.x * blockDim.x + threadIdx.x;
    if (i < n) dst[i] = __uint_as_float(f2tf32(src[i]));
}

// ---------------- embedding ----------------
__global__ void embed_kernel(const int* __restrict__ data,
                             const float* __restrict__ we,
                             const float* __restrict__ pe,
                             float* __restrict__ h) {
    int i = blockIdx.x * blockDim.x + threadIdx.x;
    if (i >= M_ROWS * Dc) return;
    int d   = i % Dc;
    int row = i / Dc;
    int s   = row % Sc;
    int tok = data[row];
    h[i] = we[(size_t)tok * Dc + d] + pe[(size_t)s * Dc + d];
}

// ---------------- tf32 tensor-core GEMM --------------------------------------
// C[M,N] = A[M,K] @ W[N,K]^T (+bias)(+res)(relu?)
// A is float (converted at fragment load); W is PRE-CONVERTED tf32 bits.
// outMode: 0 = float out, 1 = tf32-bit out
#define TBM 128
#define TBN 128
#define TBK 16
#define TPITCH 20

__global__ __launch_bounds__(256) void tgemm_kernel(
    const float* __restrict__ A, const float* __restrict__ W,
    const float* __restrict__ bias, const float* __restrict__ res,
    float* __restrict__ C, int M, int N, int K, int doRelu, int outMode)
{
    __shared__ __align__(16) float As[2][TBM][TPITCH];
    __shared__ __align__(16) float Bs[2][TBN][TPITCH];

    const int tid  = threadIdx.x;
    const int lane = tid & 31;
    const int warp = tid >> 5;
    const int wm   = warp >> 2;
    const int wn   = warp & 3;
    const int bm   = blockIdx.y * TBM;
    const int bn   = blockIdx.x * TBN;

    const int ldr = tid >> 2;
    const int kc  = (tid & 3) * 4;

    float acc[4][4][4];
    #pragma unroll
    for (int i = 0; i < 4; i++)
        #pragma unroll
        for (int j = 0; j < 4; j++)
            #pragma unroll
            for (int t = 0; t < 4; t++) acc[i][j][t] = 0.f;

    const int KT = K / TBK;

    {
        #pragma unroll
        for (int p = 0; p < 2; p++) {
            int r = ldr + p * 64;
            cp16(&As[0][r][kc], A + (size_t)(bm + r) * K + kc, 16);
        }
        #pragma unroll
        for (int p = 0; p < 2; p++) {
            int r  = ldr + p * 64;
            int gn = bn + r;
            int ok = (gn < N) ? 16 : 0;
            int gc = (gn < N) ? gn : (N - 1);
            cp16(&Bs[0][r][kc], W + (size_t)gc * K + kc, ok);
        }
        asm volatile("cp.async.commit_group;\n");
    }

    for (int t = 0; t < KT; t++) {
        asm volatile("cp.async.wait_group 0;\n");
        __syncthreads();

        if (t + 1 < KT) {
            int nb = (t + 1) & 1;
            int k0 = (t + 1) * TBK;
            #pragma unroll
            for (int p = 0; p < 2; p++) {
                int r = ldr + p * 64;
                cp16(&As[nb][r][kc], A + (size_t)(bm + r) * K + k0 + kc, 16);
            }
            #pragma unroll
            for (int p = 0; p < 2; p++) {
                int r  = ldr + p * 64;
                int gn = bn + r;
                int ok = (gn < N) ? 16 : 0;
                int gc = (gn < N) ? gn : (N - 1);
                cp16(&Bs[nb][r][kc], W + (size_t)gc * K + k0 + kc, ok);
            }
            asm volatile("cp.async.commit_group;\n");
        }

        const int buf = t & 1;
        const uint32_t* Bu = (const uint32_t*)&Bs[buf][0][0];
        #pragma unroll
        for (int ks = 0; ks < 2; ks++) {
            const int col = ks * 8 + (lane & 3);
            const int ra  = wm * 64 + (lane >> 2);
            const int rb  = wn * 32 + (lane >> 2);

            uint32_t af[4][4], bf[4][2];
            #pragma unroll
            for (int mi = 0; mi < 4; mi++) {
                af[mi][0] = f2tf32(As[buf][ra + mi * 16    ][col]);
                af[mi][1] = f2tf32(As[buf][ra + mi * 16 + 8][col]);
                af[mi][2] = f2tf32(As[buf][ra + mi * 16    ][col + 4]);
                af[mi][3] = f2tf32(As[buf][ra + mi * 16 + 8][col + 4]);
            }
            #pragma unroll
            for (int ni = 0; ni < 4; ni++) {
                bf[ni][0] = Bu[(rb + ni * 8) * TPITCH + col];      // raw tf32 bits
                bf[ni][1] = Bu[(rb + ni * 8) * TPITCH + col + 4];
            }
            #pragma unroll
            for (int mi = 0; mi < 4; mi++)
                #pragma unroll
                for (int ni = 0; ni < 4; ni++)
                    mma_tf32(acc[mi][ni], af[mi][0], af[mi][1], af[mi][2], af[mi][3],
                             bf[ni][0], bf[ni][1]);
        }
        __syncthreads();
    }

    const int lr = lane >> 2;
    const int lc = (lane & 3) * 2;
    #pragma unroll
    for (int mi = 0; mi < 4; mi++) {
        int r0 = bm + wm * 64 + mi * 16 + lr;
        #pragma unroll
        for (int ni = 0; ni < 4; ni++) {
            int c0 = bn + wn * 32 + ni * 8 + lc;
            if (c0 >= N) continue;
            float v0 = acc[mi][ni][0], v1 = acc[mi][ni][1];
            float v2 = acc[mi][ni][2], v3 = acc[mi][ni][3];
            if (bias) {
                float b0 = bias[c0], b1 = bias[c0 + 1];
                v0 += b0; v1 += b1; v2 += b0; v3 += b1;
            }
            if (res) {
                v0 += res[(size_t)r0 * N + c0];
                v1 += res[(size_t)r0 * N + c0 + 1];
                v2 += res[(size_t)(r0 + 8) * N + c0];
                v3 += res[(size_t)(r0 + 8) * N + c0 + 1];
            }
            if (doRelu) {
                v0 = fmaxf(v0, 0.f); v1 = fmaxf(v1, 0.f);
                v2 = fmaxf(v2, 0.f); v3 = fmaxf(v3, 0.f);
            }
            if (outMode) {
                v0 = __uint_as_float(f2tf32(v0));
                v1 = __uint_as_float(f2tf32(v1));
                v2 = __uint_as_float(f2tf32(v2));
                v3 = __uint_as_float(f2tf32(v3));
            }
            *(float2*)&C[(size_t)r0 * N + c0]       = make_float2(v0, v1);
            *(float2*)&C[(size_t)(r0 + 8) * N + c0] = make_float2(v2, v3);
        }
    }
}

// ---------------- tensor-core flash attention v2 ------------------------------
// Q/K/V live in the fused qkv buffer (stride 1536), already tf32 bits, Q pre-scaled.
#define AP 68
#define FATTN_SMEM ((6 * 64 * AP) * 4)

extern __shared__ float dyn_smem[];

__global__ __launch_bounds__(128) void fattn_tc(
    const float* __restrict__ Q, const float* __restrict__ Kb,
    const float* __restrict__ Vb, float* __restrict__ O)
{
    float* Qs  = dyn_smem;              // [64][AP] tf32 bits
    float* Ks  = Qs + 64 * AP;          // 2 x [64][AP]
    float* Vk  = Ks + 2 * 64 * AP;      // 2 x [64][AP]
    float* Ss  = Vk + 2 * 64 * AP;      // [64][AP] P bits

    const int qt = (gridDim.x - 1) - blockIdx.x;   // big tiles first
    const int h  = blockIdx.y, b = blockIdx.z;
    const int q0 = qt * 64;
    const int tid  = threadIdx.x;
    const int lane = tid & 31;
    const int warp = tid >> 5;

    const int OST = Hc * DHc;           // 512 (output stride)

    const int r0  = warp * 16 + (lane >> 2);
    const int cq  = lane & 3;
    const int ls4 = lane >> 2;

    // load Q tile (tf32 bits, pre-scaled)
    #pragma unroll
    for (int p = 0; p < 8; p++) {
        int c = tid + p * 128;
        int r = c >> 4, d4 = (c & 15) * 4;
        float4 v = *(const float4*)(Q + (size_t)(b * Sc + q0 + r) * QKVSTR + h * DHc + d4);
        *(float4*)&Qs[r * AP + d4] = v;
    }

    float o_acc[8][4];
    #pragma unroll
    for (int n = 0; n < 8; n++)
        #pragma unroll
        for (int t = 0; t < 4; t++) o_acc[n][t] = 0.f;
    float m0 = -1e30f, m1 = -1e30f, l0 = 0.f, l1 = 0.f;

    const int nt = qt + 1;
    const size_t kvrow0 = (size_t)(b * Sc) * QKVSTR + h * DHc;

    #pragma unroll
    for (int p = 0; p < 8; p++) {
        int c = tid + p * 128;
        int r = c >> 4, d4 = (c & 15) * 4;
        cp16(&Ks[r * AP + d4], Kb + kvrow0 + (size_t)r * QKVSTR + d4, 16);
        cp16(&Vk[r * AP + d4], Vb + kvrow0 + (size_t)r * QKVSTR + d4, 16);
    }
    asm volatile("cp.async.commit_group;\n");

    for (int kt = 0; kt < nt; kt++) {
        asm volatile("cp.async.wait_group 0;\n");
        __syncthreads();

        const int buf = kt & 1;
        if (kt + 1 < nt) {
            const int nb = buf ^ 1;
            const size_t base = kvrow0 + (size_t)(kt + 1) * 64 * QKVSTR;
            #pragma unroll
            for (int p = 0; p < 8; p++) {
                int c = tid + p * 128;
                int r = c >> 4, d4 = (c & 15) * 4;
                cp16(&Ks[nb * 64 * AP + r * AP + d4], Kb + base + (size_t)r * QKVSTR + d4, 16);
                cp16(&Vk[nb * 64 * AP + r * AP + d4], Vb + base + (size_t)r * QKVSTR + d4, 16);
            }
        }
        asm volatile("cp.async.commit_group;\n");

        const uint32_t* Qu = (const uint32_t*)Qs;
        const uint32_t* Ku = (const uint32_t*)(Ks + buf * 64 * AP);
        const uint32_t* Vu = (const uint32_t*)(Vk + buf * 64 * AP);
        uint32_t*       Pu = (uint32_t*)Ss;

        float sacc[8][4];
        #pragma unroll
        for (int n = 0; n < 8; n++)
            #pragma unroll
            for (int t = 0; t < 4; t++) sacc[n][t] = 0.f;

        #pragma unroll
        for (int k8 = 0; k8 < 8; k8++) {
            const int kcol = k8 * 8 + cq;
            uint32_t a0 = Qu[ r0      * AP + kcol];
            uint32_t a1 = Qu[(r0 + 8) * AP + kcol];
            uint32_t a2 = Qu[ r0      * AP + kcol + 4];
            uint32_t a3 = Qu[(r0 + 8) * AP + kcol + 4];
            #pragma unroll
            for (int n = 0; n < 8; n++) {
                const int nr = n * 8 + ls4;
                mma_tf32(sacc[n], a0, a1, a2, a3,
                         Ku[nr * AP + kcol], Ku[nr * AP + kcol + 4]);
            }
        }

        if (kt == qt) {
            #pragma unroll
            for (int n = 0; n < 8; n++) {
                const int c0 = n * 8 + cq * 2;
                if (c0     > r0)     sacc[n][0] = -1e30f;
                if (c0 + 1 > r0)     sacc[n][1] = -1e30f;
                if (c0     > r0 + 8) sacc[n][2] = -1e30f;
                if (c0 + 1 > r0 + 8) sacc[n][3] = -1e30f;
            }
        }

        float mx0 = -1e30f, mx1 = -1e30f;
        #pragma unroll
        for (int n = 0; n < 8; n++) {
            mx0 = fmaxf(mx0, fmaxf(sacc[n][0], sacc[n][1]));
            mx1 = fmaxf(mx1, fmaxf(sacc[n][2], sacc[n][3]));
        }
        mx0 = fmaxf(mx0, __shfl_xor_sync(0xffffffffu, mx0, 1));
        mx0 = fmaxf(mx0, __shfl_xor_sync(0xffffffffu, mx0, 2));
        mx1 = fmaxf(mx1, __shfl_xor_sync(0xffffffffu, mx1, 1));
        mx1 = fmaxf(mx1, __shfl_xor_sync(0xffffffffu, mx1, 2));

        const float mn0 = fmaxf(m0, mx0);
        const float mn1 = fmaxf(m1, mx1);
        const float cr0 = __expf(m0 - mn0);
        const float cr1 = __expf(m1 - mn1);
        float s0 = 0.f, s1 = 0.f;
        #pragma unroll
        for (int n = 0; n < 8; n++) {
            float p00 = __expf(sacc[n][0] - mn0);
            float p01 = __expf(sacc[n][1] - mn0);
            float p10 = __expf(sacc[n][2] - mn1);
            float p11 = __expf(sacc[n][3] - mn1);
            s0 += p00 + p01;
            s1 += p10 + p11;
            const int c0 = n * 8 + cq * 2;
            *(uint2*)&Pu[ r0      * AP + c0] = make_uint2(f2tf32(p00), f2tf32(p01));
            *(uint2*)&Pu[(r0 + 8) * AP + c0] = make_uint2(f2tf32(p10), f2tf32(p11));
        }
        s0 += __shfl_xor_sync(0xffffffffu, s0, 1);
        s0 += __shfl_xor_sync(0xffffffffu, s0, 2);
        s1 += __shfl_xor_sync(0xffffffffu, s1, 1);
        s1 += __shfl_xor_sync(0xffffffffu, s1, 2);

        l0 = l0 * cr0 + s0;  m0 = mn0;
        l1 = l1 * cr1 + s1;  m1 = mn1;
        #pragma unroll
        for (int n = 0; n < 8; n++) {
            o_acc[n][0] *= cr0; o_acc[n][1] *= cr0;
            o_acc[n][2] *= cr1; o_acc[n][3] *= cr1;
        }
        __syncwarp();

        #pragma unroll
        for (int k8 = 0; k8 < 8; k8++) {
            const int kcol = k8 * 8 + cq;
            uint32_t a0 = Pu[ r0      * AP + kcol];
            uint32_t a1 = Pu[(r0 + 8) * AP + kcol];
            uint32_t a2 = Pu[ r0      * AP + kcol + 4];
            uint32_t a3 = Pu[(r0 + 8) * AP + kcol + 4];
            #pragma unroll
            for (int n = 0; n < 8; n++) {
                const int nr = n * 8 + ls4;
                mma_tf32(o_acc[n], a0, a1, a2, a3,
                         Vu[kcol * AP + nr], Vu[(kcol + 4) * AP + nr]);
            }
        }
    }

    const float inv0 = 1.f / l0;
    const float inv1 = 1.f / l1;
    #pragma unroll
    for (int n = 0; n < 8; n++) {
        const int c0 = n * 8 + cq * 2;
        size_t o0 = (size_t)(b * Sc + q0 + r0)     * OST + h * DHc + c0;
        size_t o1 = (size_t)(b * Sc + q0 + r0 + 8) * OST + h * DHc + c0;
        *(float2*)&O[o0] = make_float2(o_acc[n][0] * inv0, o_acc[n][1] * inv0);
        *(float2*)&O[o1] = make_float2(o_acc[n][2] * inv1, o_acc[n][3] * inv1);
    }
}

// ---------------- LayerNorm over D=512 --------------------------------------
__global__ void ln_kernel(const float* __restrict__ X, const float* __restrict__ g,
                          const float* __restrict__ bta, float* __restrict__ Y) {
    int row = blockIdx.x;
    const float* x = X + (size_t)row * Dc;
    float* y = Y + (size_t)row * Dc;
    int tid = threadIdx.x;

    float v[4];
    float sum = 0.f;
    #pragma unroll
    for (int i = 0; i < 4; i++) { v[i] = x[tid + i*128]; sum += v[i]; }

    __shared__ float red[4];
    #pragma unroll
    for (int off = 16; off; off >>= 1) sum += __shfl_xor_sync(0xffffffffu, sum, off);
    if ((tid & 31) == 0) red[tid >> 5] = sum;
    __syncthreads();
    sum = red[0] + red[1] + red[2] + red[3];
    float mean = sum * (1.f / Dc);

    float sq = 0.f;
    #pragma unroll
    for (int i = 0; i < 4; i++) { float d = v[i] - mean; sq += d * d; }
    __shared__ float red2[4];
    #pragma unroll
    for (int off = 16; off; off >>= 1) sq += __shfl_xor_sync(0xffffffffu, sq, off);
    if ((tid & 31) == 0) red2[tid >> 5] = sq;
    __syncthreads();
    sq = red2[0] + red2[1] + red2[2] + red2[3];
    float rstd = rsqrtf(sq * (1.f / Dc) + 1e-5f);

    #pragma unroll
    for (int i = 0; i < 4; i++) {
        int d = tid + i*128;
        y[d] = (v[i] - mean) * rstd * g[d] + bta[d];
    }
}

// ---------------- launch ----------------------------------------------------
extern "C" void kernel_launch(void* const* d_in, const int* in_sizes, int n_in,
                              void* d_out, int out_size) {
    const int*   data = (const int*)  d_in[0];
    const float* we   = (const float*)d_in[1];
    const float* pe   = (const float*)d_in[2];
    const float* Wq   = (const float*)d_in[3];
    const float* Wkv  = (const float*)d_in[4];
    const float* Wo   = (const float*)d_in[5];
    const float* g1   = (const float*)d_in[6];
    const float* bl1  = (const float*)d_in[7];
    const float* W1   = (const float*)d_in[8];
    const float* bf1  = (const float*)d_in[9];
    const float* W2   = (const float*)d_in[10];
    const float* bf2  = (const float*)d_in[11];
    const float* g2   = (const float*)d_in[12];
    const float* bl2  = (const float*)d_in[13];
    const float* outb = (const float*)d_in[14];
    float* out = (float*)d_out;

    float *h, *qkv, *ao, *tmp, *ff;
    float *wqkv, *wo_t, *w1_t, *w2_t, *we_t;
    cudaGetSymbolAddress((void**)&h,    g_h);
    cudaGetSymbolAddress((void**)&qkv,  g_qkv);
    cudaGetSymbolAddress((void**)&ao,   g_ao);
    cudaGetSymbolAddress((void**)&tmp,  g_tmp);
    cudaGetSymbolAddress((void**)&ff,   g_ff);
    cudaGetSymbolAddress((void**)&wqkv, g_wqkv);
    cudaGetSymbolAddress((void**)&wo_t, g_wo_t);
    cudaGetSymbolAddress((void**)&w1_t, g_w1_t);
    cudaGetSymbolAddress((void**)&w2_t, g_w2_t);
    cudaGetSymbolAddress((void**)&we_t, g_we_t);

    cudaFuncSetAttribute(fattn_tc, cudaFuncAttributeMaxDynamicSharedMemorySize, FATTN_SMEM);

    // weight preconversion (tf32 bits)
    {
        int n;
        n = Lc * QKVSTR * Dc;  pack_qkv_w<<<(n + 255)/256, 256>>>(Wq, Wkv, wqkv);
        n = Lc * Dc * Dc;      cvt_w<<<(n + 255)/256, 256>>>(Wo, wo_t, n);
        n = Lc * DIc * Dc;     cvt_w<<<(n + 255)/256, 256>>>(W1, w1_t, n);
        n = Lc * Dc * DIc;     cvt_w<<<(n + 255)/256, 256>>>(W2, w2_t, n);
        n = Vc * Dc;           cvt_w<<<(n + 255)/256, 256>>>(we, we_t, n);
    }

    embed_kernel<<<(M_ROWS*Dc + 255)/256, 256>>>(data, we, pe, h);

    dim3 gsD  (( Dc     + 127)/128, M_ROWS/128);
    dim3 gsQKV((QKVSTR  + 127)/128, M_ROWS/128);
    dim3 gsDI (( DIc    + 127)/128, M_ROWS/128);
    dim3 gsV  (( Vc     + 127)/128, M_ROWS/128);
    dim3 gsA  (Sc/64, Hc, Bc);

    for (int l = 0; l < Lc; l++) {
        tgemm_kernel<<<gsQKV, 256>>>(h, wqkv + (size_t)l*QKVSTR*Dc, nullptr, nullptr,
                                     qkv, M_ROWS, QKVSTR, Dc, 0, 1);

        fattn_tc<<<gsA, 128, FATTN_SMEM>>>(qkv, qkv + Dc, qkv + 2*Dc, ao);

        tgemm_kernel<<<gsD, 256>>>(ao, wo_t + (size_t)l*Dc*Dc, nullptr, h, tmp,
                                   M_ROWS, Dc, Dc, 0, 0);
        ln_kernel<<<M_ROWS, 128>>>(tmp, g1 + (size_t)l*Dc, bl1 + (size_t)l*Dc, h);

        tgemm_kernel<<<gsDI, 256>>>(h, w1_t + (size_t)l*DIc*Dc, bf1 + (size_t)l*DIc, nullptr,
                                    ff, M_ROWS, DIc, Dc, 1, 0);
        tgemm_kernel<<<gsD, 256>>>(ff, w2_t + (size_t)l*Dc*DIc, bf2 + (size_t)l*Dc, h,
                                   tmp, M_ROWS, Dc, DIc, 0, 0);
        ln_kernel<<<M_ROWS, 128>>>(tmp, g2 + (size_t)l*Dc, bl2 + (size_t)l*Dc, h);
    }

    tgemm_kernel<<<gsV, 256>>>(h, we_t, outb, nullptr, out, M_ROWS, Vc, Dc, 0, 0);
}